// round 2
// baseline (speedup 1.0000x reference)
#include <cuda_runtime.h>
#include <math.h>

#define BATCH 8
#define SEQ   1024
#define HEADS 12
#define DH    64
#define DIMD  768
#define BH    (BATCH*HEADS)

// ---------------- scratch (device globals; no runtime allocation) ----------------
__device__ __align__(16) float g_Q[(size_t)BH*SEQ*DH];    // [B,H,S,dh]
__device__ __align__(16) float g_K[(size_t)BH*SEQ*DH];
__device__ __align__(16) float g_V[(size_t)BH*SEQ*DH];
__device__ __align__(16) float g_O[(size_t)BATCH*SEQ*DIMD]; // [B,S,D]

// ---------------- SGEMM: C[r][c] = A[r][:] @ W[:][c] + bias[c] ----------------
// rows = 8192, cols = 768, K = 768.  64x64 tile, 256 threads, 4x4 micro-tile, k-chunk 32.
template<bool HEAD_LAYOUT>
__global__ __launch_bounds__(256) void gemm_kernel(
    const float* __restrict__ A, const float* __restrict__ W,
    const float* __restrict__ bias, float* __restrict__ out)
{
    __shared__ float As[64][32];
    __shared__ float Bs[32][64];

    const int tid = threadIdx.x;
    const int tx  = tid & 15;          // 0..15 -> column group
    const int ty  = tid >> 4;          // 0..15 -> row group
    const int m0  = blockIdx.y * 64;
    const int n0  = blockIdx.x * 64;

    float acc[4][4] = {};

    for (int k0 = 0; k0 < DIMD; k0 += 32) {
        // load A tile 64x32 (512 float4, 2 per thread), coalesced
        #pragma unroll
        for (int it = 0; it < 2; it++) {
            int f = tid + it * 256;
            int r = f >> 3, c4 = f & 7;
            *(float4*)&As[r][c4 * 4] =
                *(const float4*)&A[(size_t)(m0 + r) * DIMD + k0 + c4 * 4];
        }
        // load W tile 32x64 (512 float4)
        #pragma unroll
        for (int it = 0; it < 2; it++) {
            int f = tid + it * 256;
            int r = f >> 4, c4 = f & 15;
            *(float4*)&Bs[r][c4 * 4] =
                *(const float4*)&W[(size_t)(k0 + r) * DIMD + n0 + c4 * 4];
        }
        __syncthreads();

        #pragma unroll
        for (int kq = 0; kq < 8; kq++) {
            float4 a4[4];
            #pragma unroll
            for (int i = 0; i < 4; i++)
                a4[i] = *(const float4*)&As[ty * 4 + i][kq * 4];
            #pragma unroll
            for (int kk = 0; kk < 4; kk++) {
                float4 b4 = *(const float4*)&Bs[kq * 4 + kk][tx * 4];
                #pragma unroll
                for (int i = 0; i < 4; i++) {
                    float a = (kk == 0) ? a4[i].x : (kk == 1) ? a4[i].y
                              : (kk == 2) ? a4[i].z : a4[i].w;
                    acc[i][0] += a * b4.x;
                    acc[i][1] += a * b4.y;
                    acc[i][2] += a * b4.z;
                    acc[i][3] += a * b4.w;
                }
            }
        }
        __syncthreads();
    }

    const int c0 = n0 + tx * 4;
    const float4 bb = *(const float4*)&bias[c0];
    #pragma unroll
    for (int i = 0; i < 4; i++) {
        int r = m0 + ty * 4 + i;
        float4 res;
        res.x = acc[i][0] + bb.x;
        res.y = acc[i][1] + bb.y;
        res.z = acc[i][2] + bb.z;
        res.w = acc[i][3] + bb.w;
        if (HEAD_LAYOUT) {
            int b = r >> 10, s = r & 1023;
            int h = c0 >> 6, j = c0 & 63;   // 4 cols stay inside one head (c0 % 64 <= 60)
            *(float4*)&out[((size_t)(b * HEADS + h) * SEQ + s) * DH + j] = res;
        } else {
            *(float4*)&out[(size_t)r * DIMD + c0] = res;
        }
    }
}

// ---------------- 2D RoPE (in place), matches reference tables exactly ----------------
// tok: [B,H,S,64]; pos: [B,S,2]. Element j: group g=j/32 uses pos[...,g];
// within group, i and i+16 share freq inv_f[i] = 100^(-i/16).
__global__ __launch_bounds__(256) void rope_kernel(
    float* __restrict__ tok, const int* __restrict__ pos)
{
    int t = blockIdx.x * blockDim.x + threadIdx.x;   // B*H*S*32 threads
    int i  = t & 15;
    int g  = (t >> 4) & 1;
    int s  = (t >> 5) & (SEQ - 1);
    int bh = t >> 15;                                 // b*HEADS + h
    if (bh >= BH) return;
    int b = bh / HEADS;

    int p = pos[((size_t)(b * SEQ + s)) * 2 + g];
    // inv_freq = 100^(-i/16) = exp(-i * ln(100)/16)
    float invf  = expf(-(float)i * (4.605170186f / 16.0f));
    float theta = (float)p * invf;
    float sn, cs;
    sincosf(theta, &sn, &cs);

    size_t base = ((size_t)bh * SEQ + s) * DH + g * 32 + i;
    float t1 = tok[base];
    float t2 = tok[base + 16];
    tok[base]      = t1 * cs - t2 * sn;
    tok[base + 16] = t2 * cs + t1 * sn;
}

// ---------------- flash attention: per (b,h), Q[1024,64] x K[1024,64] -> O ----------------
// BLOCK_N=64 q-rows per CTA, BLOCK_M=64 keys per step, 256 threads, 4x4 micro-tiles.
// K stored d-major (KsT[d][c]) in smem so column-indexed reads are conflict-free.
#define FS 68   // padded row stride (floats); 68*4B=272B -> 16B-aligned, low conflicts
__global__ __launch_bounds__(256) void flash_kernel(
    const float* __restrict__ Q, const float* __restrict__ K,
    const float* __restrict__ V, float* __restrict__ Oattn)
{
    extern __shared__ float sm[];
    float* Qs  = sm;                 // [64][FS]  row-major (r,d)
    float* KsT = sm + 64 * FS;       // [64][FS]  d-major  (d,c)
    float* Vs  = sm + 2 * 64 * FS;   // [64][FS]  row-major (m,d)
    float* Ps  = sm + 3 * 64 * FS;   // [64][FS]  row-major (r,m)

    const int tid = threadIdx.x;
    const int tx  = tid & 15;
    const int ty  = tid >> 4;
    const int bh  = blockIdx.y;          // 0..95
    const int n0  = blockIdx.x * 64;

    const float* Qb = Q + (size_t)bh * SEQ * DH;
    const float* Kb = K + (size_t)bh * SEQ * DH;
    const float* Vb = V + (size_t)bh * SEQ * DH;

    // load Q tile once
    for (int f = tid; f < 64 * 16; f += 256) {
        int r = f >> 4, dq = f & 15;
        *(float4*)&Qs[r * FS + dq * 4] = *(const float4*)&Qb[(size_t)(n0 + r) * DH + dq * 4];
    }

    float m_run[4], l_run[4], o[4][4];
    #pragma unroll
    for (int i = 0; i < 4; i++) {
        m_run[i] = -1e30f; l_run[i] = 0.f;
        #pragma unroll
        for (int j = 0; j < 4; j++) o[i][j] = 0.f;
    }

    for (int m0 = 0; m0 < SEQ; m0 += 64) {
        __syncthreads();   // previous iteration's reads of KsT/Vs/Ps done; Qs visible
        // load K (transposed into d-major) and V (natural)
        for (int f = tid; f < 64 * 16; f += 256) {
            int c = f >> 4, dq = f & 15;
            float4 kv = *(const float4*)&Kb[(size_t)(m0 + c) * DH + dq * 4];
            KsT[(dq * 4 + 0) * FS + c] = kv.x;
            KsT[(dq * 4 + 1) * FS + c] = kv.y;
            KsT[(dq * 4 + 2) * FS + c] = kv.z;
            KsT[(dq * 4 + 3) * FS + c] = kv.w;
            *(float4*)&Vs[c * FS + dq * 4] = *(const float4*)&Vb[(size_t)(m0 + c) * DH + dq * 4];
        }
        __syncthreads();

        // S = Q @ K^T  (s[i][j], rows ty*4+i, cols tx*4+j)
        float s[4][4] = {};
        #pragma unroll
        for (int dq = 0; dq < 16; dq++) {
            float4 q4[4];
            #pragma unroll
            for (int i = 0; i < 4; i++)
                q4[i] = *(const float4*)&Qs[(ty * 4 + i) * FS + dq * 4];
            #pragma unroll
            for (int kk = 0; kk < 4; kk++) {
                float4 k4 = *(const float4*)&KsT[(dq * 4 + kk) * FS + tx * 4];
                #pragma unroll
                for (int i = 0; i < 4; i++) {
                    float qv = (kk == 0) ? q4[i].x : (kk == 1) ? q4[i].y
                               : (kk == 2) ? q4[i].z : q4[i].w;
                    s[i][0] += qv * k4.x;
                    s[i][1] += qv * k4.y;
                    s[i][2] += qv * k4.z;
                    s[i][3] += qv * k4.w;
                }
            }
        }

        // online softmax update (rows shared by the 16 tx-threads; shfl over tx bits)
        #pragma unroll
        for (int i = 0; i < 4; i++) {
            float tmax = -1e30f;
            #pragma unroll
            for (int j = 0; j < 4; j++) {
                s[i][j] *= 0.125f;                 // dh^-0.5
                tmax = fmaxf(tmax, s[i][j]);
            }
            #pragma unroll
            for (int off = 1; off < 16; off <<= 1)
                tmax = fmaxf(tmax, __shfl_xor_sync(0xffffffffu, tmax, off));

            float mnew = fmaxf(m_run[i], tmax);
            float corr = __expf(m_run[i] - mnew);
            m_run[i] = mnew;

            float rsum = 0.f;
            #pragma unroll
            for (int j = 0; j < 4; j++) {
                float p = __expf(s[i][j] - mnew);
                s[i][j] = p;
                rsum += p;
            }
            #pragma unroll
            for (int off = 1; off < 16; off <<= 1)
                rsum += __shfl_xor_sync(0xffffffffu, rsum, off);

            l_run[i] = l_run[i] * corr + rsum;
            #pragma unroll
            for (int j = 0; j < 4; j++) o[i][j] *= corr;
        }

        // stage P to smem, then O += P @ V
        #pragma unroll
        for (int i = 0; i < 4; i++)
            #pragma unroll
            for (int j = 0; j < 4; j++)
                Ps[(ty * 4 + i) * FS + tx * 4 + j] = s[i][j];
        __syncthreads();

        #pragma unroll
        for (int mq = 0; mq < 16; mq++) {
            float4 p4[4];
            #pragma unroll
            for (int i = 0; i < 4; i++)
                p4[i] = *(const float4*)&Ps[(ty * 4 + i) * FS + mq * 4];
            #pragma unroll
            for (int kk = 0; kk < 4; kk++) {
                float4 v4 = *(const float4*)&Vs[(mq * 4 + kk) * FS + tx * 4];
                #pragma unroll
                for (int i = 0; i < 4; i++) {
                    float pv = (kk == 0) ? p4[i].x : (kk == 1) ? p4[i].y
                               : (kk == 2) ? p4[i].z : p4[i].w;
                    o[i][0] += pv * v4.x;
                    o[i][1] += pv * v4.y;
                    o[i][2] += pv * v4.z;
                    o[i][3] += pv * v4.w;
                }
            }
        }
    }

    // epilogue: normalize and write [B,S,D] layout for the O-projection
    const int b = bh / HEADS, h = bh % HEADS;
    #pragma unroll
    for (int i = 0; i < 4; i++) {
        float inv = 1.0f / l_run[i];
        float4 res;
        res.x = o[i][0] * inv; res.y = o[i][1] * inv;
        res.z = o[i][2] * inv; res.w = o[i][3] * inv;
        int n = n0 + ty * 4 + i;
        *(float4*)&g_O[((size_t)(b * SEQ + n)) * DIMD + h * DH + tx * 4] = res;
    }
}

// ---------------- launch ----------------
extern "C" void kernel_launch(void* const* d_in, const int* in_sizes, int n_in,
                              void* d_out, int out_size)
{
    const float* x      = (const float*)d_in[0];
    const float* y      = (const float*)d_in[1];
    const int*   pos_q  = (const int*)  d_in[2];
    const int*   pos_kv = (const int*)  d_in[3];
    const float* Wq = (const float*)d_in[4];
    const float* bq = (const float*)d_in[5];
    const float* Wk = (const float*)d_in[6];
    const float* bk = (const float*)d_in[7];
    const float* Wv = (const float*)d_in[8];
    const float* bv = (const float*)d_in[9];
    const float* Wo = (const float*)d_in[10];
    const float* bo = (const float*)d_in[11];
    float* out = (float*)d_out;

    float *Qb, *Kb, *Vb, *Ob;
    cudaGetSymbolAddress((void**)&Qb, g_Q);
    cudaGetSymbolAddress((void**)&Kb, g_K);
    cudaGetSymbolAddress((void**)&Vb, g_V);
    cudaGetSymbolAddress((void**)&Ob, g_O);

    const int SMEM_FLASH = 4 * 64 * FS * sizeof(float);  // 69,632 B
    cudaFuncSetAttribute(flash_kernel, cudaFuncAttributeMaxDynamicSharedMemorySize, SMEM_FLASH);

    dim3 ggrid(DIMD / 64, (BATCH * SEQ) / 64);   // (12, 128)

    gemm_kernel<true ><<<ggrid, 256>>>(x, Wq, bq, Qb);
    gemm_kernel<true ><<<ggrid, 256>>>(y, Wk, bk, Kb);
    gemm_kernel<true ><<<ggrid, 256>>>(y, Wv, bv, Vb);

    int rope_threads = BH * SEQ * 32;            // 3,145,728
    rope_kernel<<<rope_threads / 256, 256>>>(Qb, pos_q);
    rope_kernel<<<rope_threads / 256, 256>>>(Kb, pos_kv);

    flash_kernel<<<dim3(SEQ / 64, BH), 256, SMEM_FLASH>>>(Qb, Kb, Vb, Ob);

    gemm_kernel<false><<<ggrid, 256>>>(Ob, Wo, bo, out);
}

// round 7
// speedup vs baseline: 1.9163x; 1.9163x over previous
#include <cuda_runtime.h>
#include <mma.h>
#include <math.h>
#include <stdint.h>

using namespace nvcuda;

#define BATCH 8
#define SEQ   1024
#define HEADS 12
#define DH    64
#define DIMD  768
#define BH    (BATCH*HEADS)

// ---------------- scratch (device globals; no runtime allocation) ----------------
__device__ __align__(16) float g_Q[(size_t)BH*SEQ*DH];      // [B,H,S,dh]
__device__ __align__(16) float g_K[(size_t)BH*SEQ*DH];
__device__ __align__(16) float g_V[(size_t)BH*SEQ*DH];
__device__ __align__(16) float g_O[(size_t)BATCH*SEQ*DIMD]; // [B,S,D]
__device__ __align__(16) float g_WtQ[(size_t)DIMD*DIMD];    // W^T, tf32-rounded
__device__ __align__(16) float g_WtK[(size_t)DIMD*DIMD];
__device__ __align__(16) float g_WtV[(size_t)DIMD*DIMD];
__device__ __align__(16) float g_WtO[(size_t)DIMD*DIMD];

__device__ __forceinline__ float to_tf32(float x) {
    float r; asm("cvt.rna.tf32.f32 %0, %1;" : "=f"(r) : "f"(x)); return r;
}

// ---------------- weight transpose + tf32 round: Wt[n][k] = tf32(W[k][n]) ----------------
__global__ __launch_bounds__(256) void transpose_kernel(
    const float* __restrict__ W, float* __restrict__ Wt)
{
    __shared__ float t[32][33];
    const int bx = blockIdx.x * 32, by = blockIdx.y * 32;
    const int txl = threadIdx.x, tyl = threadIdx.y;  // (32, 8)
    #pragma unroll
    for (int j = 0; j < 32; j += 8)
        t[tyl + j][txl] = to_tf32(W[(size_t)(by + tyl + j) * DIMD + bx + txl]);
    __syncthreads();
    #pragma unroll
    for (int j = 0; j < 32; j += 8)
        Wt[(size_t)(bx + tyl + j) * DIMD + by + txl] = t[txl][tyl + j];
}

// ---------------- wmma tf32 GEMM: C[8192x768] = A @ Wt^T + bias ----------------
// CTA tile 128x64, k-chunk 16. 8 warps; each warp: 32x32 patch = 2x2 m16n16k8 frags.
// A row-major in smem (stride 20); B = Wt[n][k] loaded as col_major (stride 20).
#define BM 128
#define BN 64
#define BK 16
#define SA 20              // smem strides (floats), pad 4 to dodge bank conflicts
#define SB 20
#define LDC 68             // epilogue buffer stride (mult of 4 for store_matrix_sync)
#define SM_AS 0
#define SM_BS (BM * SA * 4)                       // 10240
#define SM_GEMM_STAGE (SM_BS + BN * SB * 4)       // 15360
#define SM_GEMM_BYTES (BM * LDC * 4)              // 34816 (epilogue reuses whole buffer)

template<bool HEAD_LAYOUT>
__global__ __launch_bounds__(256) void tc_gemm(
    const float* __restrict__ A, const float* __restrict__ Wt,
    const float* __restrict__ bias, float* __restrict__ out)
{
    extern __shared__ float sm[];
    float* As = sm;                 // [BM][SA]
    float* Bs = sm + BM * SA;       // [BN][SB]  (Bs[n][k], col-major for wmma)

    const int tid = threadIdx.x;
    const int wid = tid >> 5;
    const int m0 = blockIdx.y * BM;
    const int n0 = blockIdx.x * BN;
    const int m_warp = (wid >> 1) * 32;   // 0,32,64,96
    const int n_warp = (wid & 1) * 32;    // 0,32

    wmma::fragment<wmma::accumulator, 16, 16, 8, float> acc[2][2];
    #pragma unroll
    for (int i = 0; i < 2; i++)
        #pragma unroll
        for (int j = 0; j < 2; j++)
            wmma::fill_fragment(acc[i][j], 0.0f);

    for (int k0 = 0; k0 < DIMD; k0 += BK) {
        // stage A [128 rows][16 k] with tf32 rounding: 512 float4, 2/thread
        #pragma unroll
        for (int it = 0; it < 2; it++) {
            int f = tid + it * 256;
            int r = f >> 2, c4 = f & 3;
            float4 v = *(const float4*)&A[(size_t)(m0 + r) * DIMD + k0 + c4 * 4];
            v.x = to_tf32(v.x); v.y = to_tf32(v.y); v.z = to_tf32(v.z); v.w = to_tf32(v.w);
            *(float4*)&As[r * SA + c4 * 4] = v;
        }
        // stage B = Wt[n0..n0+63][k0..k0+15] (already tf32): 256 float4, 1/thread
        {
            int r = tid >> 2, c4 = tid & 3;
            *(float4*)&Bs[r * SB + c4 * 4] =
                *(const float4*)&Wt[(size_t)(n0 + r) * DIMD + k0 + c4 * 4];
        }
        __syncthreads();

        #pragma unroll
        for (int kk = 0; kk < BK; kk += 8) {
            wmma::fragment<wmma::matrix_a, 16, 16, 8, wmma::precision::tf32, wmma::row_major> fa[2];
            wmma::fragment<wmma::matrix_b, 16, 16, 8, wmma::precision::tf32, wmma::col_major> fb[2];
            #pragma unroll
            for (int i = 0; i < 2; i++) {
                wmma::load_matrix_sync(fa[i], &As[(m_warp + i * 16) * SA + kk], SA);
                #pragma unroll
                for (int e = 0; e < fa[i].num_elements; e++)
                    fa[i].x[e] = wmma::__float_to_tf32(fa[i].x[e]);
            }
            #pragma unroll
            for (int j = 0; j < 2; j++) {
                wmma::load_matrix_sync(fb[j], &Bs[(n_warp + j * 16) * SB + kk], SB);
                #pragma unroll
                for (int e = 0; e < fb[j].num_elements; e++)
                    fb[j].x[e] = wmma::__float_to_tf32(fb[j].x[e]);
            }
            #pragma unroll
            for (int i = 0; i < 2; i++)
                #pragma unroll
                for (int j = 0; j < 2; j++)
                    wmma::mma_sync(acc[i][j], fa[i], fb[j], acc[i][j]);
        }
        __syncthreads();
    }

    // epilogue: park accumulators in smem (reuses stage area), then coalesced writes
    float* Cs = sm;   // [BM][LDC]
    #pragma unroll
    for (int i = 0; i < 2; i++)
        #pragma unroll
        for (int j = 0; j < 2; j++)
            wmma::store_matrix_sync(&Cs[(m_warp + i * 16) * LDC + n_warp + j * 16],
                                    acc[i][j], LDC, wmma::mem_row_major);
    __syncthreads();

    // 128x64 tile = 2048 float4, 8 per thread
    #pragma unroll
    for (int it = 0; it < 8; it++) {
        int f = tid + it * 256;
        int r = f >> 4, c4 = f & 15;
        const int c = n0 + c4 * 4;
        float4 res = *(float4*)&Cs[r * LDC + c4 * 4];
        const float4 bb = *(const float4*)&bias[c];
        res.x += bb.x; res.y += bb.y; res.z += bb.z; res.w += bb.w;
        const int rg = m0 + r;
        if (HEAD_LAYOUT) {
            int b = rg >> 10, s = rg & 1023;
            int h = c >> 6, j = c & 63;
            *(float4*)&out[((size_t)(b * HEADS + h) * SEQ + s) * DH + j] = res;
        } else {
            *(float4*)&out[(size_t)rg * DIMD + c] = res;
        }
    }
}

// ---------------- 2D RoPE (in place) — unchanged from passing R2 ----------------
__global__ __launch_bounds__(256) void rope_kernel(
    float* __restrict__ tok, const int* __restrict__ pos)
{
    int t = blockIdx.x * blockDim.x + threadIdx.x;
    int i  = t & 15;
    int g  = (t >> 4) & 1;
    int s  = (t >> 5) & (SEQ - 1);
    int bh = t >> 15;
    if (bh >= BH) return;
    int b = bh / HEADS;

    int p = pos[((size_t)(b * SEQ + s)) * 2 + g];
    float invf  = expf(-(float)i * (4.605170186f / 16.0f));
    float theta = (float)p * invf;
    float sn, cs;
    sincosf(theta, &sn, &cs);

    size_t base = ((size_t)bh * SEQ + s) * DH + g * 32 + i;
    float t1 = tok[base];
    float t2 = tok[base + 16];
    tok[base]      = t1 * cs - t2 * sn;
    tok[base + 16] = t2 * cs + t1 * sn;
}

// ---------------- flash attention — unchanged from passing R2 ----------------
#define FS 68
__global__ __launch_bounds__(256) void flash_kernel(
    const float* __restrict__ Q, const float* __restrict__ K,
    const float* __restrict__ V)
{
    extern __shared__ float smf[];
    float* Qs  = smf;
    float* KsT = smf + 64 * FS;
    float* Vs  = smf + 2 * 64 * FS;
    float* Ps  = smf + 3 * 64 * FS;

    const int tid = threadIdx.x;
    const int tx  = tid & 15;
    const int ty  = tid >> 4;
    const int bh  = blockIdx.y;
    const int n0  = blockIdx.x * 64;

    const float* Qb = Q + (size_t)bh * SEQ * DH;
    const float* Kb = K + (size_t)bh * SEQ * DH;
    const float* Vb = V + (size_t)bh * SEQ * DH;

    for (int f = tid; f < 64 * 16; f += 256) {
        int r = f >> 4, dq = f & 15;
        *(float4*)&Qs[r * FS + dq * 4] = *(const float4*)&Qb[(size_t)(n0 + r) * DH + dq * 4];
    }

    float m_run[4], l_run[4], o[4][4];
    #pragma unroll
    for (int i = 0; i < 4; i++) {
        m_run[i] = -1e30f; l_run[i] = 0.f;
        #pragma unroll
        for (int j = 0; j < 4; j++) o[i][j] = 0.f;
    }

    for (int m0 = 0; m0 < SEQ; m0 += 64) {
        __syncthreads();
        for (int f = tid; f < 64 * 16; f += 256) {
            int c = f >> 4, dq = f & 15;
            float4 kv = *(const float4*)&Kb[(size_t)(m0 + c) * DH + dq * 4];
            KsT[(dq * 4 + 0) * FS + c] = kv.x;
            KsT[(dq * 4 + 1) * FS + c] = kv.y;
            KsT[(dq * 4 + 2) * FS + c] = kv.z;
            KsT[(dq * 4 + 3) * FS + c] = kv.w;
            *(float4*)&Vs[c * FS + dq * 4] = *(const float4*)&Vb[(size_t)(m0 + c) * DH + dq * 4];
        }
        __syncthreads();

        float s[4][4] = {};
        #pragma unroll
        for (int dq = 0; dq < 16; dq++) {
            float4 q4[4];
            #pragma unroll
            for (int i = 0; i < 4; i++)
                q4[i] = *(const float4*)&Qs[(ty * 4 + i) * FS + dq * 4];
            #pragma unroll
            for (int kk = 0; kk < 4; kk++) {
                float4 k4 = *(const float4*)&KsT[(dq * 4 + kk) * FS + tx * 4];
                #pragma unroll
                for (int i = 0; i < 4; i++) {
                    float qv = (kk == 0) ? q4[i].x : (kk == 1) ? q4[i].y
                               : (kk == 2) ? q4[i].z : q4[i].w;
                    s[i][0] += qv * k4.x;
                    s[i][1] += qv * k4.y;
                    s[i][2] += qv * k4.z;
                    s[i][3] += qv * k4.w;
                }
            }
        }

        #pragma unroll
        for (int i = 0; i < 4; i++) {
            float tmax = -1e30f;
            #pragma unroll
            for (int j = 0; j < 4; j++) {
                s[i][j] *= 0.125f;
                tmax = fmaxf(tmax, s[i][j]);
            }
            #pragma unroll
            for (int off = 1; off < 16; off <<= 1)
                tmax = fmaxf(tmax, __shfl_xor_sync(0xffffffffu, tmax, off));

            float mnew = fmaxf(m_run[i], tmax);
            float corr = __expf(m_run[i] - mnew);
            m_run[i] = mnew;

            float rsum = 0.f;
            #pragma unroll
            for (int j = 0; j < 4; j++) {
                float p = __expf(s[i][j] - mnew);
                s[i][j] = p;
                rsum += p;
            }
            #pragma unroll
            for (int off = 1; off < 16; off <<= 1)
                rsum += __shfl_xor_sync(0xffffffffu, rsum, off);

            l_run[i] = l_run[i] * corr + rsum;
            #pragma unroll
            for (int j = 0; j < 4; j++) o[i][j] *= corr;
        }

        #pragma unroll
        for (int i = 0; i < 4; i++)
            #pragma unroll
            for (int j = 0; j < 4; j++)
                Ps[(ty * 4 + i) * FS + tx * 4 + j] = s[i][j];
        __syncthreads();

        #pragma unroll
        for (int mq = 0; mq < 16; mq++) {
            float4 p4[4];
            #pragma unroll
            for (int i = 0; i < 4; i++)
                p4[i] = *(const float4*)&Ps[(ty * 4 + i) * FS + mq * 4];
            #pragma unroll
            for (int kk = 0; kk < 4; kk++) {
                float4 v4 = *(const float4*)&Vs[(mq * 4 + kk) * FS + tx * 4];
                #pragma unroll
                for (int i = 0; i < 4; i++) {
                    float pv = (kk == 0) ? p4[i].x : (kk == 1) ? p4[i].y
                               : (kk == 2) ? p4[i].z : p4[i].w;
                    o[i][0] += pv * v4.x;
                    o[i][1] += pv * v4.y;
                    o[i][2] += pv * v4.z;
                    o[i][3] += pv * v4.w;
                }
            }
        }
    }

    const int b = bh / HEADS, h = bh % HEADS;
    #pragma unroll
    for (int i = 0; i < 4; i++) {
        float inv = 1.0f / l_run[i];
        float4 res;
        res.x = o[i][0] * inv; res.y = o[i][1] * inv;
        res.z = o[i][2] * inv; res.w = o[i][3] * inv;
        int n = n0 + ty * 4 + i;
        *(float4*)&g_O[((size_t)(b * SEQ + n)) * DIMD + h * DH + tx * 4] = res;
    }
}

// ---------------- launch ----------------
extern "C" void kernel_launch(void* const* d_in, const int* in_sizes, int n_in,
                              void* d_out, int out_size)
{
    const float* x      = (const float*)d_in[0];
    const float* y      = (const float*)d_in[1];
    const int*   pos_q  = (const int*)  d_in[2];
    const int*   pos_kv = (const int*)  d_in[3];
    const float* Wq = (const float*)d_in[4];
    const float* bq = (const float*)d_in[5];
    const float* Wk = (const float*)d_in[6];
    const float* bk = (const float*)d_in[7];
    const float* Wv = (const float*)d_in[8];
    const float* bv = (const float*)d_in[9];
    const float* Wo = (const float*)d_in[10];
    const float* bo = (const float*)d_in[11];
    float* out = (float*)d_out;

    float *Qb, *Kb, *Vb, *Ob, *WtQ, *WtK, *WtV, *WtO;
    cudaGetSymbolAddress((void**)&Qb,  g_Q);
    cudaGetSymbolAddress((void**)&Kb,  g_K);
    cudaGetSymbolAddress((void**)&Vb,  g_V);
    cudaGetSymbolAddress((void**)&Ob,  g_O);
    cudaGetSymbolAddress((void**)&WtQ, g_WtQ);
    cudaGetSymbolAddress((void**)&WtK, g_WtK);
    cudaGetSymbolAddress((void**)&WtV, g_WtV);
    cudaGetSymbolAddress((void**)&WtO, g_WtO);

    const int SMEM_FLASH = 4 * 64 * FS * sizeof(float);  // 69,632 B
    cudaFuncSetAttribute(flash_kernel, cudaFuncAttributeMaxDynamicSharedMemorySize, SMEM_FLASH);
    cudaFuncSetAttribute(tc_gemm<true >, cudaFuncAttributeMaxDynamicSharedMemorySize, SM_GEMM_BYTES);
    cudaFuncSetAttribute(tc_gemm<false>, cudaFuncAttributeMaxDynamicSharedMemorySize, SM_GEMM_BYTES);

    dim3 tgrid(DIMD / 32, DIMD / 32);            // (24, 24)
    dim3 tblk(32, 8);
    transpose_kernel<<<tgrid, tblk>>>(Wq, WtQ);
    transpose_kernel<<<tgrid, tblk>>>(Wk, WtK);
    transpose_kernel<<<tgrid, tblk>>>(Wv, WtV);
    transpose_kernel<<<tgrid, tblk>>>(Wo, WtO);

    dim3 ggrid(DIMD / BN, (BATCH * SEQ) / BM);   // (12, 64)
    tc_gemm<true ><<<ggrid, 256, SM_GEMM_BYTES>>>(x, WtQ, bq, Qb);
    tc_gemm<true ><<<ggrid, 256, SM_GEMM_BYTES>>>(y, WtK, bk, Kb);
    tc_gemm<true ><<<ggrid, 256, SM_GEMM_BYTES>>>(y, WtV, bv, Vb);

    int rope_threads = BH * SEQ * 32;
    rope_kernel<<<rope_threads / 256, 256>>>(Qb, pos_q);
    rope_kernel<<<rope_threads / 256, 256>>>(Kb, pos_kv);

    flash_kernel<<<dim3(SEQ / 64, BH), 256, SMEM_FLASH>>>(Qb, Kb, Vb);

    tc_gemm<false><<<ggrid, 256, SM_GEMM_BYTES>>>(Ob, WtO, bo, out);
}

// round 16
// speedup vs baseline: 2.1774x; 1.1363x over previous
#include <cuda_runtime.h>
#include <mma.h>
#include <math.h>
#include <stdint.h>

using namespace nvcuda;

#define BATCH 8
#define SEQ   1024
#define HEADS 12
#define DH    64
#define DIMD  768
#define BH    (BATCH*HEADS)

// ---------------- scratch (device globals; no runtime allocation) ----------------
__device__ __align__(16) float g_Q[(size_t)BH*SEQ*DH];      // [B,H,S,dh]
__device__ __align__(16) float g_K[(size_t)BH*SEQ*DH];
__device__ __align__(16) float g_V[(size_t)BH*SEQ*DH];
__device__ __align__(16) float g_O[(size_t)BATCH*SEQ*DIMD]; // [B,S,D]
__device__ __align__(16) float g_WtQ[(size_t)DIMD*DIMD];    // W^T, tf32-rounded
__device__ __align__(16) float g_WtK[(size_t)DIMD*DIMD];
__device__ __align__(16) float g_WtV[(size_t)DIMD*DIMD];
__device__ __align__(16) float g_WtO[(size_t)DIMD*DIMD];

__device__ __forceinline__ float to_tf32(float x) {
    float r; asm("cvt.rna.tf32.f32 %0, %1;" : "=f"(r) : "f"(x)); return r;
}

// ---------------- weight transpose + tf32 round: Wt[n][k] = tf32(W[k][n]) ----------------
__global__ __launch_bounds__(256) void transpose_kernel(
    const float* __restrict__ W, float* __restrict__ Wt)
{
    __shared__ float t[32][33];
    const int bx = blockIdx.x * 32, by = blockIdx.y * 32;
    const int txl = threadIdx.x, tyl = threadIdx.y;  // (32, 8)
    #pragma unroll
    for (int j = 0; j < 32; j += 8)
        t[tyl + j][txl] = to_tf32(W[(size_t)(by + tyl + j) * DIMD + bx + txl]);
    __syncthreads();
    #pragma unroll
    for (int j = 0; j < 32; j += 8)
        Wt[(size_t)(bx + tyl + j) * DIMD + by + txl] = t[txl][tyl + j];
}

// ---------------- wmma tf32 GEMM: C[8192x768] = A @ Wt^T + bias (unchanged, R7 WIN) ----------------
#define BM 128
#define BN 64
#define BK 16
#define SA 20
#define SB 20
#define LDC 68
#define SM_GEMM_BYTES (BM * LDC * 4)              // 34816

template<bool HEAD_LAYOUT>
__global__ __launch_bounds__(256) void tc_gemm(
    const float* __restrict__ A, const float* __restrict__ Wt,
    const float* __restrict__ bias, float* __restrict__ out)
{
    extern __shared__ float sm[];
    float* As = sm;                 // [BM][SA]
    float* Bs = sm + BM * SA;       // [BN][SB]

    const int tid = threadIdx.x;
    const int wid = tid >> 5;
    const int m0 = blockIdx.y * BM;
    const int n0 = blockIdx.x * BN;
    const int m_warp = (wid >> 1) * 32;
    const int n_warp = (wid & 1) * 32;

    wmma::fragment<wmma::accumulator, 16, 16, 8, float> acc[2][2];
    #pragma unroll
    for (int i = 0; i < 2; i++)
        #pragma unroll
        for (int j = 0; j < 2; j++)
            wmma::fill_fragment(acc[i][j], 0.0f);

    for (int k0 = 0; k0 < DIMD; k0 += BK) {
        #pragma unroll
        for (int it = 0; it < 2; it++) {
            int f = tid + it * 256;
            int r = f >> 2, c4 = f & 3;
            float4 v = *(const float4*)&A[(size_t)(m0 + r) * DIMD + k0 + c4 * 4];
            v.x = to_tf32(v.x); v.y = to_tf32(v.y); v.z = to_tf32(v.z); v.w = to_tf32(v.w);
            *(float4*)&As[r * SA + c4 * 4] = v;
        }
        {
            int r = tid >> 2, c4 = tid & 3;
            *(float4*)&Bs[r * SB + c4 * 4] =
                *(const float4*)&Wt[(size_t)(n0 + r) * DIMD + k0 + c4 * 4];
        }
        __syncthreads();

        #pragma unroll
        for (int kk = 0; kk < BK; kk += 8) {
            wmma::fragment<wmma::matrix_a, 16, 16, 8, wmma::precision::tf32, wmma::row_major> fa[2];
            wmma::fragment<wmma::matrix_b, 16, 16, 8, wmma::precision::tf32, wmma::col_major> fb[2];
            #pragma unroll
            for (int i = 0; i < 2; i++) {
                wmma::load_matrix_sync(fa[i], &As[(m_warp + i * 16) * SA + kk], SA);
                #pragma unroll
                for (int e = 0; e < fa[i].num_elements; e++)
                    fa[i].x[e] = wmma::__float_to_tf32(fa[i].x[e]);
            }
            #pragma unroll
            for (int j = 0; j < 2; j++) {
                wmma::load_matrix_sync(fb[j], &Bs[(n_warp + j * 16) * SB + kk], SB);
                #pragma unroll
                for (int e = 0; e < fb[j].num_elements; e++)
                    fb[j].x[e] = wmma::__float_to_tf32(fb[j].x[e]);
            }
            #pragma unroll
            for (int i = 0; i < 2; i++)
                #pragma unroll
                for (int j = 0; j < 2; j++)
                    wmma::mma_sync(acc[i][j], fa[i], fb[j], acc[i][j]);
        }
        __syncthreads();
    }

    float* Cs = sm;   // [BM][LDC]
    #pragma unroll
    for (int i = 0; i < 2; i++)
        #pragma unroll
        for (int j = 0; j < 2; j++)
            wmma::store_matrix_sync(&Cs[(m_warp + i * 16) * LDC + n_warp + j * 16],
                                    acc[i][j], LDC, wmma::mem_row_major);
    __syncthreads();

    #pragma unroll
    for (int it = 0; it < 8; it++) {
        int f = tid + it * 256;
        int r = f >> 4, c4 = f & 15;
        const int c = n0 + c4 * 4;
        float4 res = *(float4*)&Cs[r * LDC + c4 * 4];
        const float4 bb = *(const float4*)&bias[c];
        res.x += bb.x; res.y += bb.y; res.z += bb.z; res.w += bb.w;
        const int rg = m0 + r;
        if (HEAD_LAYOUT) {
            int b = rg >> 10, s = rg & 1023;
            int h = c >> 6, j = c & 63;
            *(float4*)&out[((size_t)(b * HEADS + h) * SEQ + s) * DH + j] = res;
        } else {
            *(float4*)&out[(size_t)rg * DIMD + c] = res;
        }
    }
}

// ---------------- 2D RoPE (in place) — unchanged ----------------
__global__ __launch_bounds__(256) void rope_kernel(
    float* __restrict__ tok, const int* __restrict__ pos)
{
    int t = blockIdx.x * blockDim.x + threadIdx.x;
    int i  = t & 15;
    int g  = (t >> 4) & 1;
    int s  = (t >> 5) & (SEQ - 1);
    int bh = t >> 15;
    if (bh >= BH) return;
    int b = bh / HEADS;

    int p = pos[((size_t)(b * SEQ + s)) * 2 + g];
    float invf  = expf(-(float)i * (4.605170186f / 16.0f));
    float theta = (float)p * invf;
    float sn, cs;
    sincosf(theta, &sn, &cs);

    size_t base = ((size_t)bh * SEQ + s) * DH + g * 32 + i;
    float t1 = tok[base];
    float t2 = tok[base + 16];
    tok[base]      = t1 * cs - t2 * sn;
    tok[base + 16] = t2 * cs + t1 * sn;
}

// ---------------- wmma flash attention ----------------
// CTA: 128 q-rows, loop over KV in 16 blocks of 64. 8 warps (4x2 warp grid, 2x2 frags).
// Online softmax: thread pair (2t,2t+1) owns row t (32 cols each half); O accumulated
// in scalar regs with per-row corr; P@V uses fresh accumulators each block.
#define FSS 68
#define QS_OFF 0
#define KS_OFF (128 * FSS)              // 8704
#define VS_OFF (KS_OFF + 64 * FSS)      // 13056
#define SS_OFF (VS_OFF + 64 * FSS)      // 17408
#define SM_FLASH_BYTES ((SS_OFF + 128 * FSS) * 4)   // 104448

__global__ __launch_bounds__(256) void flash_wmma(
    const float* __restrict__ Q, const float* __restrict__ K,
    const float* __restrict__ V)
{
    extern __shared__ float smf[];
    float* Qs = smf + QS_OFF;   // [128][FSS]
    float* Ks = smf + KS_OFF;   // [64][FSS]
    float* Vs = smf + VS_OFF;   // [64][FSS]
    float* Ss = smf + SS_OFF;   // [128][FSS]  (S -> P -> O_blk)

    const int tid = threadIdx.x;
    const int wid = tid >> 5;
    const int bh  = blockIdx.y;
    const int n0  = blockIdx.x * 128;
    const int m_warp = (wid >> 1) * 32;
    const int n_warp = (wid & 1) * 32;
    const int row = tid >> 1;            // 0..127
    const int cb  = (tid & 1) * 32;      // column half

    const float* Qb = Q + (size_t)bh * SEQ * DH;
    const float* Kb = K + (size_t)bh * SEQ * DH;
    const float* Vb = V + (size_t)bh * SEQ * DH;

    // stage Q once (tf32-rounded): 128 rows x 16 float4 = 2048, 8/thread
    #pragma unroll
    for (int it = 0; it < 8; it++) {
        int f = tid + it * 256;
        int r = f >> 4, c4 = f & 15;
        float4 v = *(const float4*)&Qb[(size_t)(n0 + r) * DH + c4 * 4];
        v.x = to_tf32(v.x); v.y = to_tf32(v.y); v.z = to_tf32(v.z); v.w = to_tf32(v.w);
        *(float4*)&Qs[r * FSS + c4 * 4] = v;
    }

    float m_run = -1e30f, l_run = 0.0f;
    float O_run[32];
    #pragma unroll
    for (int j = 0; j < 32; j++) O_run[j] = 0.0f;

    for (int m0 = 0; m0 < SEQ; m0 += 64) {
        // stage K and V blocks (tf32-rounded): 64 x 16 float4 each, 4/thread each
        #pragma unroll
        for (int it = 0; it < 4; it++) {
            int f = tid + it * 256;
            int r = f >> 4, c4 = f & 15;
            float4 kv = *(const float4*)&Kb[(size_t)(m0 + r) * DH + c4 * 4];
            kv.x = to_tf32(kv.x); kv.y = to_tf32(kv.y); kv.z = to_tf32(kv.z); kv.w = to_tf32(kv.w);
            *(float4*)&Ks[r * FSS + c4 * 4] = kv;
            float4 vv = *(const float4*)&Vb[(size_t)(m0 + r) * DH + c4 * 4];
            vv.x = to_tf32(vv.x); vv.y = to_tf32(vv.y); vv.z = to_tf32(vv.z); vv.w = to_tf32(vv.w);
            *(float4*)&Vs[r * FSS + c4 * 4] = vv;
        }
        __syncthreads();   // K/V ready; also: prev accumulate done before Ss overwrite

        // ---- S = Q @ K^T  (128x64, K=64) ----
        {
            wmma::fragment<wmma::accumulator, 16, 16, 8, float> acc[2][2];
            #pragma unroll
            for (int i = 0; i < 2; i++)
                #pragma unroll
                for (int j = 0; j < 2; j++)
                    wmma::fill_fragment(acc[i][j], 0.0f);
            #pragma unroll
            for (int kk = 0; kk < DH; kk += 8) {
                wmma::fragment<wmma::matrix_a, 16, 16, 8, wmma::precision::tf32, wmma::row_major> fa[2];
                wmma::fragment<wmma::matrix_b, 16, 16, 8, wmma::precision::tf32, wmma::col_major> fb[2];
                #pragma unroll
                for (int i = 0; i < 2; i++) {
                    wmma::load_matrix_sync(fa[i], &Qs[(m_warp + i * 16) * FSS + kk], FSS);
                    #pragma unroll
                    for (int e = 0; e < fa[i].num_elements; e++)
                        fa[i].x[e] = wmma::__float_to_tf32(fa[i].x[e]);
                }
                #pragma unroll
                for (int j = 0; j < 2; j++) {
                    wmma::load_matrix_sync(fb[j], &Ks[(n_warp + j * 16) * FSS + kk], FSS);
                    #pragma unroll
                    for (int e = 0; e < fb[j].num_elements; e++)
                        fb[j].x[e] = wmma::__float_to_tf32(fb[j].x[e]);
                }
                #pragma unroll
                for (int i = 0; i < 2; i++)
                    #pragma unroll
                    for (int j = 0; j < 2; j++)
                        wmma::mma_sync(acc[i][j], fa[i], fb[j], acc[i][j]);
            }
            #pragma unroll
            for (int i = 0; i < 2; i++)
                #pragma unroll
                for (int j = 0; j < 2; j++)
                    wmma::store_matrix_sync(&Ss[(m_warp + i * 16) * FSS + n_warp + j * 16],
                                            acc[i][j], FSS, wmma::mem_row_major);
        }
        __syncthreads();

        // ---- online softmax (thread pair per row; partner = lane^1) ----
        float corr;
        {
            float sv[32];
            #pragma unroll
            for (int j4 = 0; j4 < 8; j4++) {
                float4 s4 = *(float4*)&Ss[row * FSS + cb + j4 * 4];
                sv[j4 * 4 + 0] = s4.x * 0.125f;
                sv[j4 * 4 + 1] = s4.y * 0.125f;
                sv[j4 * 4 + 2] = s4.z * 0.125f;
                sv[j4 * 4 + 3] = s4.w * 0.125f;
            }
            float bmax = -1e30f;
            #pragma unroll
            for (int j = 0; j < 32; j++) bmax = fmaxf(bmax, sv[j]);
            bmax = fmaxf(bmax, __shfl_xor_sync(0xffffffffu, bmax, 1));

            float mnew = fmaxf(m_run, bmax);
            corr = __expf(m_run - mnew);
            m_run = mnew;

            float rsum = 0.0f;
            #pragma unroll
            for (int j4 = 0; j4 < 8; j4++) {
                float4 p4;
                float p0 = __expf(sv[j4 * 4 + 0] - mnew);
                float p1 = __expf(sv[j4 * 4 + 1] - mnew);
                float p2 = __expf(sv[j4 * 4 + 2] - mnew);
                float p3 = __expf(sv[j4 * 4 + 3] - mnew);
                rsum += p0 + p1 + p2 + p3;
                p4.x = to_tf32(p0); p4.y = to_tf32(p1);
                p4.z = to_tf32(p2); p4.w = to_tf32(p3);
                *(float4*)&Ss[row * FSS + cb + j4 * 4] = p4;
            }
            rsum += __shfl_xor_sync(0xffffffffu, rsum, 1);
            l_run = l_run * corr + rsum;
        }
        __syncthreads();

        // ---- O_blk = P @ V  (128x64, K=64), fresh accumulators ----
        {
            wmma::fragment<wmma::accumulator, 16, 16, 8, float> acc[2][2];
            #pragma unroll
            for (int i = 0; i < 2; i++)
                #pragma unroll
                for (int j = 0; j < 2; j++)
                    wmma::fill_fragment(acc[i][j], 0.0f);
            #pragma unroll
            for (int kk = 0; kk < 64; kk += 8) {
                wmma::fragment<wmma::matrix_a, 16, 16, 8, wmma::precision::tf32, wmma::row_major> fa[2];
                wmma::fragment<wmma::matrix_b, 16, 16, 8, wmma::precision::tf32, wmma::row_major> fb[2];
                #pragma unroll
                for (int i = 0; i < 2; i++) {
                    wmma::load_matrix_sync(fa[i], &Ss[(m_warp + i * 16) * FSS + kk], FSS);
                    #pragma unroll
                    for (int e = 0; e < fa[i].num_elements; e++)
                        fa[i].x[e] = wmma::__float_to_tf32(fa[i].x[e]);
                }
                #pragma unroll
                for (int j = 0; j < 2; j++) {
                    wmma::load_matrix_sync(fb[j], &Vs[kk * FSS + n_warp + j * 16], FSS);
                    #pragma unroll
                    for (int e = 0; e < fb[j].num_elements; e++)
                        fb[j].x[e] = wmma::__float_to_tf32(fb[j].x[e]);
                }
                #pragma unroll
                for (int i = 0; i < 2; i++)
                    #pragma unroll
                    for (int j = 0; j < 2; j++)
                        wmma::mma_sync(acc[i][j], fa[i], fb[j], acc[i][j]);
            }
            __syncthreads();   // all warps finished reading P from Ss
            #pragma unroll
            for (int i = 0; i < 2; i++)
                #pragma unroll
                for (int j = 0; j < 2; j++)
                    wmma::store_matrix_sync(&Ss[(m_warp + i * 16) * FSS + n_warp + j * 16],
                                            acc[i][j], FSS, wmma::mem_row_major);
        }
        __syncthreads();

        // ---- scalar online accumulate with known row ownership ----
        #pragma unroll
        for (int j4 = 0; j4 < 8; j4++) {
            float4 o4 = *(float4*)&Ss[row * FSS + cb + j4 * 4];
            O_run[j4 * 4 + 0] = O_run[j4 * 4 + 0] * corr + o4.x;
            O_run[j4 * 4 + 1] = O_run[j4 * 4 + 1] * corr + o4.y;
            O_run[j4 * 4 + 2] = O_run[j4 * 4 + 2] * corr + o4.z;
            O_run[j4 * 4 + 3] = O_run[j4 * 4 + 3] * corr + o4.w;
        }
        // next iteration's first __syncthreads() orders these reads vs Ss overwrite
    }

    // epilogue: normalize and write [B,S,D]
    const int b = bh / HEADS, h = bh % HEADS;
    const float inv = 1.0f / l_run;
    const int n = n0 + row;
    #pragma unroll
    for (int j4 = 0; j4 < 8; j4++) {
        float4 res;
        res.x = O_run[j4 * 4 + 0] * inv;
        res.y = O_run[j4 * 4 + 1] * inv;
        res.z = O_run[j4 * 4 + 2] * inv;
        res.w = O_run[j4 * 4 + 3] * inv;
        *(float4*)&g_O[((size_t)(b * SEQ + n)) * DIMD + h * DH + cb + j4 * 4] = res;
    }
}

// ---------------- launch ----------------
extern "C" void kernel_launch(void* const* d_in, const int* in_sizes, int n_in,
                              void* d_out, int out_size)
{
    const float* x      = (const float*)d_in[0];
    const float* y      = (const float*)d_in[1];
    const int*   pos_q  = (const int*)  d_in[2];
    const int*   pos_kv = (const int*)  d_in[3];
    const float* Wq = (const float*)d_in[4];
    const float* bq = (const float*)d_in[5];
    const float* Wk = (const float*)d_in[6];
    const float* bk = (const float*)d_in[7];
    const float* Wv = (const float*)d_in[8];
    const float* bv = (const float*)d_in[9];
    const float* Wo = (const float*)d_in[10];
    const float* bo = (const float*)d_in[11];
    float* out = (float*)d_out;

    float *Qb, *Kb, *Vb, *Ob, *WtQ, *WtK, *WtV, *WtO;
    cudaGetSymbolAddress((void**)&Qb,  g_Q);
    cudaGetSymbolAddress((void**)&Kb,  g_K);
    cudaGetSymbolAddress((void**)&Vb,  g_V);
    cudaGetSymbolAddress((void**)&Ob,  g_O);
    cudaGetSymbolAddress((void**)&WtQ, g_WtQ);
    cudaGetSymbolAddress((void**)&WtK, g_WtK);
    cudaGetSymbolAddress((void**)&WtV, g_WtV);
    cudaGetSymbolAddress((void**)&WtO, g_WtO);

    cudaFuncSetAttribute(flash_wmma, cudaFuncAttributeMaxDynamicSharedMemorySize, SM_FLASH_BYTES);
    cudaFuncSetAttribute(tc_gemm<true >, cudaFuncAttributeMaxDynamicSharedMemorySize, SM_GEMM_BYTES);
    cudaFuncSetAttribute(tc_gemm<false>, cudaFuncAttributeMaxDynamicSharedMemorySize, SM_GEMM_BYTES);

    dim3 tgrid(DIMD / 32, DIMD / 32);
    dim3 tblk(32, 8);
    transpose_kernel<<<tgrid, tblk>>>(Wq, WtQ);
    transpose_kernel<<<tgrid, tblk>>>(Wk, WtK);
    transpose_kernel<<<tgrid, tblk>>>(Wv, WtV);
    transpose_kernel<<<tgrid, tblk>>>(Wo, WtO);

    dim3 ggrid(DIMD / BN, (BATCH * SEQ) / BM);   // (12, 64)
    tc_gemm<true ><<<ggrid, 256, SM_GEMM_BYTES>>>(x, WtQ, bq, Qb);
    tc_gemm<true ><<<ggrid, 256, SM_GEMM_BYTES>>>(y, WtK, bk, Kb);
    tc_gemm<true ><<<ggrid, 256, SM_GEMM_BYTES>>>(y, WtV, bv, Vb);

    int rope_threads = BH * SEQ * 32;
    rope_kernel<<<rope_threads / 256, 256>>>(Qb, pos_q);
    rope_kernel<<<rope_threads / 256, 256>>>(Kb, pos_kv);

    flash_wmma<<<dim3(SEQ / 128, BH), 256, SM_FLASH_BYTES>>>(Qb, Kb, Vb);

    tc_gemm<false><<<ggrid, 256, SM_GEMM_BYTES>>>(Ob, WtO, bo, out);
}